// round 15
// baseline (speedup 1.0000x reference)
#include <cuda_runtime.h>
#include <cstdint>

// ---------------------------------------------------------------------------
// WindowAttention round 14:
//  K0 : round qkv_w / proj_w to tf32; prep combined (bias+mask)*log2e
//  K1 : qkv GEMM, tf32 mma.sync, 3-stage single-sync cp.async pipeline
//  K2 : tensor-core attention; comb tile staged to smem via cp.async
//  K3 : proj GEMM (same engine as K1)
// ---------------------------------------------------------------------------

#define BATCH   4096
#define NTOK    49
#define EMB     384
#define HEADS   12
#define HD      32
#define NWIN    64
#define MROWS   (BATCH * NTOK)        // 200704
#define QKV_O   (3 * EMB)             // 1152
#define KDIM    384

#define SSTR    36
#define ABUF    (128 * SSTR)          // floats per tile buffer (18432 B)
#define SMEM_BYTES (6 * ABUF * 4)     // 3-stage A + B = 110592 B

// padded attention dims
#define NTP     64
#define NSP     56

__device__ float g_qkv[(size_t)3 * BATCH * HEADS * NTOK * HD];
__device__ float g_y [(size_t)MROWS * EMB];
__device__ float g_wq[QKV_O * KDIM];
__device__ float g_wp[EMB * KDIM];
__device__ float g_comb[(size_t)NWIN * HEADS * NTP * NSP];   // 11 MB

__device__ __forceinline__ float tf32r(float x) {
    uint32_t r;
    asm("cvt.rna.tf32.f32 %0, %1;" : "=r"(r) : "f"(x));
    return __uint_as_float(r);
}
__device__ __forceinline__ float ex2(float x) {
    float y;
    asm("ex2.approx.f32 %0, %1;" : "=f"(y) : "f"(x));
    return y;
}
__device__ __forceinline__ void cpa16(uint32_t dst, const float* src) {
    asm volatile("cp.async.ca.shared.global [%0], [%1], 16;"
                 :: "r"(dst), "l"(src));
}
__device__ __forceinline__ void mma_tf32(
    float c[4], const uint32_t a[4], uint32_t b0, uint32_t b1)
{
    asm volatile(
        "mma.sync.aligned.m16n8k8.row.col.f32.tf32.tf32.f32 "
        "{%0,%1,%2,%3},{%4,%5,%6,%7},{%8,%9},{%0,%1,%2,%3};"
        : "+f"(c[0]), "+f"(c[1]), "+f"(c[2]), "+f"(c[3])
        : "r"(a[0]), "r"(a[1]), "r"(a[2]), "r"(a[3]), "r"(b0), "r"(b1));
}

// ---------------------------------------------------------------------------
// K0a: weight rounding (tiny). DST: 1 = g_wq, 2 = g_wp
// ---------------------------------------------------------------------------
template <int DST>
__global__ void cvt_tf32_kernel(const float4* __restrict__ in, int n4)
{
    int i = blockIdx.x * blockDim.x + threadIdx.x;
    if (i >= n4) return;
    float4 v = in[i];
    v.x = tf32r(v.x); v.y = tf32r(v.y); v.z = tf32r(v.z); v.w = tf32r(v.w);
    float4* outp = (DST == 1) ? (float4*)g_wq : (float4*)g_wp;
    outp[i] = v;
}

// ---------------------------------------------------------------------------
// K0b: combined table, scaled by log2(e)
// ---------------------------------------------------------------------------
__global__ void prep_bias(const float* __restrict__ mask,
                          const float* __restrict__ rpb,
                          const int* __restrict__ rel_idx)
{
    int idx = blockIdx.x * blockDim.x + threadIdx.x;
    const int total = NWIN * HEADS * NTP * NSP;
    if (idx >= total) return;
    int j = idx % NSP;
    int i = (idx / NSP) % NTP;
    int h = (idx / (NSP * NTP)) % HEADS;
    int w = idx / (NSP * NTP * HEADS);
    float v = -1e30f;
    if (i < NTOK && j < NTOK)
        v = (mask[((size_t)w * NTOK + i) * NTOK + j]
           + rpb[rel_idx[i * NTOK + j] * HEADS + h]) * 1.4426950408889634f;
    g_comb[idx] = v;
}

// ---------------------------------------------------------------------------
// K1/K3: tf32 MMA GEMM, 3-stage cp.async pipeline, ONE sync per chunk.
// MODE 0: A = x (rounded in-fragment), W = g_wq, scatter -> g_qkv.
// MODE 1: A = g_y, W = g_wp, -> out.
// ---------------------------------------------------------------------------
template <int MODE>
__global__ void __launch_bounds__(128, 2) mma_gemm(
    const float* __restrict__ Aext,
    const float* __restrict__ bias, float* __restrict__ out)
{
    extern __shared__ float smem[];   // [A0|A1|A2|B0|B1|B2]

    const float* A = (MODE == 0) ? Aext : g_y;
    const float* W = (MODE == 0) ? g_wq : g_wp;

    const int t     = threadIdx.x;
    const int mBase = blockIdx.y * 128;
    const int oBase = blockIdx.x * 128;
    const int warp  = t >> 5, lane = t & 31;
    const int g     = lane >> 2, tig = lane & 3;
    const int mOff  = (warp & 1) * 64;
    const int nOff  = (warp >> 1) * 64;

    const float* Ap = A + (size_t)mBase * KDIM;
    const float* Wp = W + (size_t)oBase * KDIM;

    const int lr = t >> 3;
    const int kq = (t & 7) << 2;
    const uint32_t sA = (uint32_t)__cvta_generic_to_shared(smem);

    float acc[4][8][4];
#pragma unroll
    for (int mi = 0; mi < 4; mi++)
#pragma unroll
        for (int ni = 0; ni < 8; ni++)
#pragma unroll
            for (int j = 0; j < 4; j++) acc[mi][ni][j] = 0.f;

    auto load_chunk = [&](int c, int buf) {
        uint32_t aB = sA + (uint32_t)(buf * ABUF) * 4u;
        uint32_t bB = sA + (uint32_t)((3 + buf) * ABUF) * 4u;
        const int k0 = c * 32;
#pragma unroll
        for (int i = 0; i < 8; i++) {
            int row = lr + 16 * i;
            cpa16(aB + (uint32_t)(row * SSTR + kq) * 4u,
                  Ap + (size_t)row * KDIM + k0 + kq);
            cpa16(bB + (uint32_t)(row * SSTR + kq) * 4u,
                  Wp + (size_t)row * KDIM + k0 + kq);
        }
        asm volatile("cp.async.commit_group;");
    };

    auto ldA = [&](const float* p) -> uint32_t {
        float v = *p;
        if (MODE == 0) v = tf32r(v);
        return __float_as_uint(v);
    };

    load_chunk(0, 0);
    load_chunk(1, 1);

    const int NCHk = KDIM / 32;           // 12
    int buf = 0;
    for (int c = 0; c < NCHk; c++) {
        if (c + 1 < NCHk)
            asm volatile("cp.async.wait_group 1;");   // chunk c arrived
        else
            asm volatile("cp.async.wait_group 0;");
        __syncthreads();                              // single barrier/chunk

        if (c + 2 < NCHk) {
            int nbuf = buf + 2; if (nbuf >= 3) nbuf -= 3;
            load_chunk(c + 2, nbuf);  // writes buffer read at c-1: safe
        }

        const float* Asb = smem + buf * ABUF;
        const float* Bsb = smem + (3 + buf) * ABUF;

#pragma unroll
        for (int kk = 0; kk < 32; kk += 8) {
            uint32_t a[4][4], b[8][2];
#pragma unroll
            for (int mi = 0; mi < 4; mi++) {
                int r = mOff + mi * 16 + g;
                a[mi][0] = ldA(&Asb[r * SSTR + kk + tig]);
                a[mi][1] = ldA(&Asb[(r + 8) * SSTR + kk + tig]);
                a[mi][2] = ldA(&Asb[r * SSTR + kk + tig + 4]);
                a[mi][3] = ldA(&Asb[(r + 8) * SSTR + kk + tig + 4]);
            }
#pragma unroll
            for (int ni = 0; ni < 8; ni++) {
                int cc = nOff + ni * 8 + g;
                b[ni][0] = __float_as_uint(Bsb[cc * SSTR + kk + tig]);
                b[ni][1] = __float_as_uint(Bsb[cc * SSTR + kk + tig + 4]);
            }
#pragma unroll
            for (int mi = 0; mi < 4; mi++)
#pragma unroll
                for (int ni = 0; ni < 8; ni++)
                    mma_tf32(acc[mi][ni], a[mi], b[ni][0], b[ni][1]);
        }

        buf++; if (buf >= 3) buf -= 3;
    }

#pragma unroll
    for (int mi = 0; mi < 4; mi++) {
#pragma unroll
        for (int ni = 0; ni < 8; ni++) {
            int col = oBase + nOff + ni * 8 + 2 * tig;
            float b0 = __ldg(bias + col);
            float b1 = __ldg(bias + col + 1);
#pragma unroll
            for (int half = 0; half < 2; half++) {
                int m = mBase + mOff + mi * 16 + g + half * 8;
                float v0 = acc[mi][ni][2 * half + 0] + b0;
                float v1 = acc[mi][ni][2 * half + 1] + b1;
                if (MODE == 0) {
                    int s = col / EMB;
                    int r = col - s * EMB;
                    int h = r >> 5;
                    int bb = m / NTOK;
                    int nn = m - bb * NTOK;
                    size_t idx = ((((size_t)s * BATCH + bb) * HEADS + h) * NTOK
                                  + nn) * HD + (r & 31);
                    *(float2*)&g_qkv[idx] = make_float2(v0, v1);
                } else {
                    *(float2*)&out[(size_t)m * EMB + col] = make_float2(v0, v1);
                }
            }
        }
    }
}

// ---------------------------------------------------------------------------
// K2: tensor-core attention. One CTA (128 thr) per (b,h).
// smem: K hi/lo + V^T + comb tile (cp.async-staged). Q fragments from gmem.
// ---------------------------------------------------------------------------
#define KSTR 33
#define VSTR 57
#define OFF_KH 0
#define OFF_KL (NSP * KSTR)                   // 1848
#define OFF_VT (2 * NSP * KSTR)               // 3696
#define OFF_CB (OFF_VT + HD * VSTR)           // 5520
#define SM_TOT (OFF_CB + NTP * NSP)           // 5520 + 3584 = 9104 floats

__global__ void __launch_bounds__(128, 6) attn_kernel()
{
    const int b = blockIdx.x;
    const int h = blockIdx.y;
    const int tid = threadIdx.x;

    __shared__ __align__(16) float sm[SM_TOT];

    // 1) fire comb tile cp.async first (rows 0..48 only; rows >=49 feed
    //    discarded outputs, garbage confined)
    {
        const float* combsrc = g_comb
            + (((size_t)(b & (NWIN - 1)) * HEADS + h) * NTP) * NSP;
        uint32_t cbB = (uint32_t)__cvta_generic_to_shared(sm + OFF_CB);
        for (int i = tid; i < (NTOK * NSP) / 4; i += 128)   // 686 xfers
            cpa16(cbB + 16u * i, combsrc + 4 * i);
        asm volatile("cp.async.commit_group;");
    }

    // 2) zero K/V padding
    for (int i = tid; i < 7 * KSTR; i += 128) {
        sm[OFF_KH + 49 * KSTR + i] = 0.f;
        sm[OFF_KL + 49 * KSTR + i] = 0.f;
    }
    for (int i = tid; i < HD * 8; i += 128)
        sm[OFF_VT + (i >> 3) * VSTR + 49 + (i & 7)] = 0.f;

    const size_t stride = (size_t)NTOK * HD;
    const size_t qoff = (((size_t)0 * BATCH + b) * HEADS + h) * stride;
    const size_t koff = (((size_t)1 * BATCH + b) * HEADS + h) * stride;
    const size_t voff = (((size_t)2 * BATCH + b) * HEADS + h) * stride;

    // 3) stage K (hi/lo) and V^T (overlaps with comb cp.async)
    for (int i = tid; i < (NTOK * HD) / 4; i += 128) {
        int row = i >> 3, col = (i & 7) * 4;
        float4 k = ((const float4*)(g_qkv + koff))[i];
        float4 v = ((const float4*)(g_qkv + voff))[i];
        float ka[4] = {k.x, k.y, k.z, k.w};
        float va[4] = {v.x, v.y, v.z, v.w};
#pragma unroll
        for (int c = 0; c < 4; c++) {
            float kh = tf32r(ka[c]);
            sm[OFF_KH + row * KSTR + col + c] = kh;
            sm[OFF_KL + row * KSTR + col + c] = tf32r(ka[c] - kh);
            sm[OFF_VT + (col + c) * VSTR + row] = tf32r(va[c]);
        }
    }
    asm volatile("cp.async.wait_group 0;");
    __syncthreads();

    const int wid  = tid >> 5, lane = tid & 31;
    const int g    = lane >> 2, t = lane & 3;
    const int r0   = wid * 16 + g;          // rows r0, r0+8 (garbage if >=49)

    const float* gq = g_qkv + qoff;

    float c[7][4];
#pragma unroll
    for (int j = 0; j < 7; j++)
#pragma unroll
        for (int q = 0; q < 4; q++) c[j][q] = 0.f;

    // QK^T: kc outer; Q fragments from gmem with register hi/lo split
#pragma unroll
    for (int kc = 0; kc < 4; kc++) {
        const int cb = kc * 8 + t;
        float q0 = __ldg(gq + (size_t)r0 * HD + cb);
        float q1 = __ldg(gq + (size_t)(r0 + 8) * HD + cb);
        float q2 = __ldg(gq + (size_t)r0 * HD + cb + 4);
        float q3 = __ldg(gq + (size_t)(r0 + 8) * HD + cb + 4);
        float h0 = tf32r(q0), h1 = tf32r(q1), h2 = tf32r(q2), h3 = tf32r(q3);
        uint32_t ah[4] = {__float_as_uint(h0), __float_as_uint(h1),
                          __float_as_uint(h2), __float_as_uint(h3)};
        uint32_t al[4] = {__float_as_uint(tf32r(q0 - h0)),
                          __float_as_uint(tf32r(q1 - h1)),
                          __float_as_uint(tf32r(q2 - h2)),
                          __float_as_uint(tf32r(q3 - h3))};
#pragma unroll
        for (int j = 0; j < 7; j++) {
            int krow = (j * 8 + g) * KSTR + kc * 8 + t;
            uint32_t bh0 = __float_as_uint(sm[OFF_KH + krow]);
            uint32_t bh1 = __float_as_uint(sm[OFF_KH + krow + 4]);
            uint32_t bl0 = __float_as_uint(sm[OFF_KL + krow]);
            uint32_t bl1 = __float_as_uint(sm[OFF_KL + krow + 4]);
            mma_tf32(c[j], ah, bh0, bh1);
            mma_tf32(c[j], ah, bl0, bl1);
            mma_tf32(c[j], al, bh0, bh1);
        }
    }

    // P = exp2(c*scale*log2e + comb) with comb from smem
    const float scale2 = 0.17677669529663687f * 1.4426950408889634f;
    const float* combs = sm + OFF_CB;

    float s0 = 0.f, s1 = 0.f;
#pragma unroll
    for (int j = 0; j < 7; j++) {
        float2 m0 = *(const float2*)(combs + r0 * NSP + j * 8 + 2 * t);
        float2 m1 = *(const float2*)(combs + (r0 + 8) * NSP + j * 8 + 2 * t);
        float e0 = ex2(fmaf(c[j][0], scale2, m0.x));
        float e1 = ex2(fmaf(c[j][1], scale2, m0.y));
        float e2 = ex2(fmaf(c[j][2], scale2, m1.x));
        float e3 = ex2(fmaf(c[j][3], scale2, m1.y));
        s0 += e0 + e1; s1 += e2 + e3;
        c[j][0] = tf32r(e0); c[j][1] = tf32r(e1);
        c[j][2] = tf32r(e2); c[j][3] = tf32r(e3);
    }
    s0 += __shfl_xor_sync(0xffffffffu, s0, 1);
    s0 += __shfl_xor_sync(0xffffffffu, s0, 2);
    s1 += __shfl_xor_sync(0xffffffffu, s1, 1);
    s1 += __shfl_xor_sync(0xffffffffu, s1, 2);
    const float inv0 = 1.0f / s0, inv1 = 1.0f / s1;

    // AV: P (c-frag -> a-frag via shfl) x V^T
    float acc[4][4];
#pragma unroll
    for (int n = 0; n < 4; n++)
#pragma unroll
        for (int q = 0; q < 4; q++) acc[n][q] = 0.f;

#pragma unroll
    for (int j = 0; j < 7; j++) {
        int src = (g << 2) + (t >> 1);
        float v0 = __shfl_sync(0xffffffffu, c[j][0], src);
        float v1 = __shfl_sync(0xffffffffu, c[j][1], src);
        float v2 = __shfl_sync(0xffffffffu, c[j][2], src);
        float v3 = __shfl_sync(0xffffffffu, c[j][3], src);
        float w0 = __shfl_sync(0xffffffffu, c[j][0], src + 2);
        float w1 = __shfl_sync(0xffffffffu, c[j][1], src + 2);
        float w2 = __shfl_sync(0xffffffffu, c[j][2], src + 2);
        float w3 = __shfl_sync(0xffffffffu, c[j][3], src + 2);
        uint32_t a[4];
        a[0] = __float_as_uint((t & 1) ? v1 : v0);
        a[1] = __float_as_uint((t & 1) ? v3 : v2);
        a[2] = __float_as_uint((t & 1) ? w1 : w0);
        a[3] = __float_as_uint((t & 1) ? w3 : w2);
#pragma unroll
        for (int n = 0; n < 4; n++) {
            int vrow = (n * 8 + g) * VSTR + j * 8 + t;
            uint32_t b0 = __float_as_uint(sm[OFF_VT + vrow]);
            uint32_t b1 = __float_as_uint(sm[OFF_VT + vrow + 4]);
            mma_tf32(acc[n], a, b0, b1);
        }
    }

#pragma unroll
    for (int n = 0; n < 4; n++) {
        int col = h * HD + n * 8 + 2 * t;
        if (r0 < NTOK) {
            float2 o = make_float2(tf32r(acc[n][0] * inv0),
                                   tf32r(acc[n][1] * inv0));
            *(float2*)&g_y[((size_t)b * NTOK + r0) * EMB + col] = o;
        }
        if (r0 + 8 < NTOK) {
            float2 o = make_float2(tf32r(acc[n][2] * inv1),
                                   tf32r(acc[n][3] * inv1));
            *(float2*)&g_y[((size_t)b * NTOK + r0 + 8) * EMB + col] = o;
        }
    }
}

// ---------------------------------------------------------------------------
extern "C" void kernel_launch(void* const* d_in, const int* in_sizes, int n_in,
                              void* d_out, int out_size)
{
    const float* x      = (const float*)d_in[0];
    const float* mask   = (const float*)d_in[1];
    const float* qkv_w  = (const float*)d_in[2];
    const float* qkv_b  = (const float*)d_in[3];
    const float* proj_w = (const float*)d_in[4];
    const float* proj_b = (const float*)d_in[5];
    const float* rpb    = (const float*)d_in[6];
    const int*   rel_idx= (const int*)  d_in[7];
    float* out = (float*)d_out;

    cudaFuncSetAttribute(mma_gemm<0>,
        cudaFuncAttributeMaxDynamicSharedMemorySize, SMEM_BYTES);
    cudaFuncSetAttribute(mma_gemm<1>,
        cudaFuncAttributeMaxDynamicSharedMemorySize, SMEM_BYTES);

    // K0: weight rounding (tiny) + combined bias table
    {
        int w4 = QKV_O * KDIM / 4;
        cvt_tf32_kernel<1><<<(w4 + 255) / 256, 256>>>((const float4*)qkv_w, w4);
        int p4 = EMB * KDIM / 4;
        cvt_tf32_kernel<2><<<(p4 + 255) / 256, 256>>>((const float4*)proj_w, p4);
        int nb = NWIN * HEADS * NTP * NSP;
        prep_bias<<<(nb + 255) / 256, 256>>>(mask, rpb, rel_idx);
    }
    // K1: qkv GEMM (x rounded in-fragment)
    {
        dim3 grid(QKV_O / 128, MROWS / 128);
        mma_gemm<0><<<grid, 128, SMEM_BYTES>>>(x, qkv_b, nullptr);
    }
    // K2: attention
    {
        dim3 grid(BATCH, HEADS);
        attn_kernel<<<grid, 128>>>();
    }
    // K3: proj GEMM
    {
        dim3 grid(EMB / 128, MROWS / 128);
        mma_gemm<1><<<grid, 128, SMEM_BYTES>>>(g_y /*unused*/, proj_b, out);
    }
}

// round 17
// speedup vs baseline: 1.2637x; 1.2637x over previous
#include <cuda_runtime.h>
#include <cstdint>

// ---------------------------------------------------------------------------
// WindowAttention round 15:
//  K0 : round qkv_w / proj_w to tf32; prep combined (bias+mask)*log2e
//  K1 : qkv GEMM, tf32 mma.sync, 2-stage cp.async (reverted from 3-stage),
//       fragment loads via ldmatrix.m8n8.x4.b16 (4x fewer smem instructions)
//  K2 : tensor-core attention; comb tile staged to smem via cp.async
//  K3 : proj GEMM (same engine)
// ---------------------------------------------------------------------------

#define BATCH   4096
#define NTOK    49
#define EMB     384
#define HEADS   12
#define HD      32
#define NWIN    64
#define MROWS   (BATCH * NTOK)        // 200704
#define QKV_O   (3 * EMB)             // 1152
#define KDIM    384

#define SSTR    36                    // smem row stride (floats); 144B rows
#define ABUF    (128 * SSTR)
#define SMEM_BYTES (4 * ABUF * 4)     // 73728 B (2 CTAs/SM fit)

// padded attention dims
#define NTP     64
#define NSP     56

__device__ float g_qkv[(size_t)3 * BATCH * HEADS * NTOK * HD];
__device__ float g_y [(size_t)MROWS * EMB];
__device__ float g_wq[QKV_O * KDIM];
__device__ float g_wp[EMB * KDIM];
__device__ float g_comb[(size_t)NWIN * HEADS * NTP * NSP];   // 11 MB

__device__ __forceinline__ float tf32r(float x) {
    uint32_t r;
    asm("cvt.rna.tf32.f32 %0, %1;" : "=r"(r) : "f"(x));
    return __uint_as_float(r);
}
__device__ __forceinline__ uint32_t tf32ru(uint32_t x) {
    uint32_t r;
    asm("cvt.rna.tf32.f32 %0, %1;" : "=r"(r) : "f"(__uint_as_float(x)));
    return r;
}
__device__ __forceinline__ float ex2(float x) {
    float y;
    asm("ex2.approx.f32 %0, %1;" : "=f"(y) : "f"(x));
    return y;
}
__device__ __forceinline__ void cpa16(uint32_t dst, const float* src) {
    asm volatile("cp.async.ca.shared.global [%0], [%1], 16;"
                 :: "r"(dst), "l"(src));
}
__device__ __forceinline__ void mma_tf32(
    float c[4], const uint32_t a[4], uint32_t b0, uint32_t b1)
{
    asm volatile(
        "mma.sync.aligned.m16n8k8.row.col.f32.tf32.tf32.f32 "
        "{%0,%1,%2,%3},{%4,%5,%6,%7},{%8,%9},{%0,%1,%2,%3};"
        : "+f"(c[0]), "+f"(c[1]), "+f"(c[2]), "+f"(c[3])
        : "r"(a[0]), "r"(a[1]), "r"(a[2]), "r"(a[3]), "r"(b0), "r"(b1));
}
__device__ __forceinline__ void ldsm4(
    uint32_t& r0, uint32_t& r1, uint32_t& r2, uint32_t& r3, uint32_t addr)
{
    asm volatile("ldmatrix.sync.aligned.m8n8.x4.shared.b16 {%0,%1,%2,%3}, [%4];"
                 : "=r"(r0), "=r"(r1), "=r"(r2), "=r"(r3) : "r"(addr));
}

// ---------------------------------------------------------------------------
// K0a: weight rounding. DST: 1 = g_wq, 2 = g_wp
// ---------------------------------------------------------------------------
template <int DST>
__global__ void cvt_tf32_kernel(const float4* __restrict__ in, int n4)
{
    int i = blockIdx.x * blockDim.x + threadIdx.x;
    if (i >= n4) return;
    float4 v = in[i];
    v.x = tf32r(v.x); v.y = tf32r(v.y); v.z = tf32r(v.z); v.w = tf32r(v.w);
    float4* outp = (DST == 1) ? (float4*)g_wq : (float4*)g_wp;
    outp[i] = v;
}

// ---------------------------------------------------------------------------
// K0b: combined table, scaled by log2(e)
// ---------------------------------------------------------------------------
__global__ void prep_bias(const float* __restrict__ mask,
                          const float* __restrict__ rpb,
                          const int* __restrict__ rel_idx)
{
    int idx = blockIdx.x * blockDim.x + threadIdx.x;
    const int total = NWIN * HEADS * NTP * NSP;
    if (idx >= total) return;
    int j = idx % NSP;
    int i = (idx / NSP) % NTP;
    int h = (idx / (NSP * NTP)) % HEADS;
    int w = idx / (NSP * NTP * HEADS);
    float v = -1e30f;
    if (i < NTOK && j < NTOK)
        v = (mask[((size_t)w * NTOK + i) * NTOK + j]
           + rpb[rel_idx[i * NTOK + j] * HEADS + h]) * 1.4426950408889634f;
    g_comb[idx] = v;
}

// ---------------------------------------------------------------------------
// K1/K3: tf32 MMA GEMM, 2-stage cp.async, ldmatrix fragment loads.
// MODE 0: A = x (tf32-rounded post-LDSM), W = g_wq, scatter -> g_qkv.
// MODE 1: A = g_y, W = g_wp, -> out.
// ---------------------------------------------------------------------------
template <int MODE>
__global__ void __launch_bounds__(128, 2) mma_gemm(
    const float* __restrict__ Aext,
    const float* __restrict__ bias, float* __restrict__ out)
{
    extern __shared__ float smem[];   // [A0|A1|B0|B1]

    const float* A = (MODE == 0) ? Aext : g_y;
    const float* W = (MODE == 0) ? g_wq : g_wp;

    const int t     = threadIdx.x;
    const int mBase = blockIdx.y * 128;
    const int oBase = blockIdx.x * 128;
    const int warp  = t >> 5, lane = t & 31;
    const int g     = lane >> 2, tig = lane & 3;
    const int mOff  = (warp & 1) * 64;
    const int nOff  = (warp >> 1) * 64;

    const float* Ap = A + (size_t)mBase * KDIM;
    const float* Wp = W + (size_t)oBase * KDIM;

    const int lr = t >> 3;
    const int kq = (t & 7) << 2;
    const uint32_t sA = (uint32_t)__cvta_generic_to_shared(smem);

    // ldmatrix lane geometry: tile index lT (0..3), row-in-tile lrow (0..7)
    const int lT   = lane >> 3;
    const int lrow = lane & 7;
    // A tiles: T0 rows +0..7 cols kk, T1 rows +8 cols kk,
    //          T2 rows +0 cols kk+4, T3 rows +8 cols kk+4
    const int aRow = mOff + ((lT & 1) << 3) + lrow;
    const int aCol = (lT >> 1) << 2;
    // B tiles (per pair p): T0 rows 2p*8 cols kk, T1 same rows cols kk+4,
    //                       T2 rows (2p+1)*8 cols kk, T3 cols kk+4
    const int bRow = nOff + ((lT >> 1) << 3) + lrow;
    const int bCol = (lT & 1) << 2;

    float acc[4][8][4];
#pragma unroll
    for (int mi = 0; mi < 4; mi++)
#pragma unroll
        for (int ni = 0; ni < 8; ni++)
#pragma unroll
            for (int j = 0; j < 4; j++) acc[mi][ni][j] = 0.f;

    auto load_chunk = [&](int k0, int buf) {
        uint32_t aB = sA + (uint32_t)(buf * ABUF) * 4u;
        uint32_t bB = sA + (uint32_t)((2 + buf) * ABUF) * 4u;
#pragma unroll
        for (int i = 0; i < 8; i++) {
            int row = lr + 16 * i;
            cpa16(aB + (uint32_t)(row * SSTR + kq) * 4u,
                  Ap + (size_t)row * KDIM + k0 + kq);
            cpa16(bB + (uint32_t)(row * SSTR + kq) * 4u,
                  Wp + (size_t)row * KDIM + k0 + kq);
        }
        asm volatile("cp.async.commit_group;");
    };

    load_chunk(0, 0);

    const int NCHk = KDIM / 32;           // 12
    for (int c = 0; c < NCHk; c++) {
        if (c + 1 < NCHk) {
            load_chunk((c + 1) * 32, (c + 1) & 1);
            asm volatile("cp.async.wait_group 1;");
        } else {
            asm volatile("cp.async.wait_group 0;");
        }
        __syncthreads();

        const uint32_t aBase = sA + (uint32_t)((c & 1) * ABUF) * 4u
                             + (uint32_t)(aRow * SSTR + aCol) * 4u;
        const uint32_t bBase = sA + (uint32_t)((2 + (c & 1)) * ABUF) * 4u
                             + (uint32_t)(bRow * SSTR + bCol) * 4u;

#pragma unroll
        for (int kk = 0; kk < 32; kk += 8) {
            uint32_t a[4][4], b2[4][4];
#pragma unroll
            for (int mi = 0; mi < 4; mi++)
                ldsm4(a[mi][0], a[mi][1], a[mi][2], a[mi][3],
                      aBase + (uint32_t)(mi * 16 * SSTR + kk) * 4u);
            if (MODE == 0) {
#pragma unroll
                for (int mi = 0; mi < 4; mi++)
#pragma unroll
                    for (int j = 0; j < 4; j++)
                        a[mi][j] = tf32ru(a[mi][j]);
            }
#pragma unroll
            for (int p = 0; p < 4; p++)
                ldsm4(b2[p][0], b2[p][1], b2[p][2], b2[p][3],
                      bBase + (uint32_t)(p * 16 * SSTR + kk) * 4u);
#pragma unroll
            for (int mi = 0; mi < 4; mi++)
#pragma unroll
                for (int p = 0; p < 4; p++) {
                    mma_tf32(acc[mi][2 * p],     a[mi], b2[p][0], b2[p][1]);
                    mma_tf32(acc[mi][2 * p + 1], a[mi], b2[p][2], b2[p][3]);
                }
        }
        __syncthreads();
    }

#pragma unroll
    for (int mi = 0; mi < 4; mi++) {
#pragma unroll
        for (int ni = 0; ni < 8; ni++) {
            int col = oBase + nOff + ni * 8 + 2 * tig;
            float b0 = __ldg(bias + col);
            float b1 = __ldg(bias + col + 1);
#pragma unroll
            for (int half = 0; half < 2; half++) {
                int m = mBase + mOff + mi * 16 + g + half * 8;
                float v0 = acc[mi][ni][2 * half + 0] + b0;
                float v1 = acc[mi][ni][2 * half + 1] + b1;
                if (MODE == 0) {
                    int s = col / EMB;
                    int r = col - s * EMB;
                    int h = r >> 5;
                    int bb = m / NTOK;
                    int nn = m - bb * NTOK;
                    size_t idx = ((((size_t)s * BATCH + bb) * HEADS + h) * NTOK
                                  + nn) * HD + (r & 31);
                    *(float2*)&g_qkv[idx] = make_float2(v0, v1);
                } else {
                    *(float2*)&out[(size_t)m * EMB + col] = make_float2(v0, v1);
                }
            }
        }
    }
}

// ---------------------------------------------------------------------------
// K2: tensor-core attention (round-14 version). One CTA (128 thr) per (b,h).
// smem: K hi/lo + V^T + comb tile (cp.async-staged). Q fragments from gmem.
// ---------------------------------------------------------------------------
#define KSTR 33
#define VSTR 57
#define OFF_KH 0
#define OFF_KL (NSP * KSTR)                   // 1848
#define OFF_VT (2 * NSP * KSTR)               // 3696
#define OFF_CB (OFF_VT + HD * VSTR)           // 5520
#define SM_TOT (OFF_CB + NTP * NSP)           // 9104 floats

__global__ void __launch_bounds__(128, 6) attn_kernel()
{
    const int b = blockIdx.x;
    const int h = blockIdx.y;
    const int tid = threadIdx.x;

    __shared__ __align__(16) float sm[SM_TOT];

    // 1) comb tile via cp.async (rows 0..48; later rows feed discarded output)
    {
        const float* combsrc = g_comb
            + (((size_t)(b & (NWIN - 1)) * HEADS + h) * NTP) * NSP;
        uint32_t cbB = (uint32_t)__cvta_generic_to_shared(sm + OFF_CB);
        for (int i = tid; i < (NTOK * NSP) / 4; i += 128)
            cpa16(cbB + 16u * i, combsrc + 4 * i);
        asm volatile("cp.async.commit_group;");
    }

    // 2) zero K/V padding
    for (int i = tid; i < 7 * KSTR; i += 128) {
        sm[OFF_KH + 49 * KSTR + i] = 0.f;
        sm[OFF_KL + 49 * KSTR + i] = 0.f;
    }
    for (int i = tid; i < HD * 8; i += 128)
        sm[OFF_VT + (i >> 3) * VSTR + 49 + (i & 7)] = 0.f;

    const size_t stride = (size_t)NTOK * HD;
    const size_t qoff = (((size_t)0 * BATCH + b) * HEADS + h) * stride;
    const size_t koff = (((size_t)1 * BATCH + b) * HEADS + h) * stride;
    const size_t voff = (((size_t)2 * BATCH + b) * HEADS + h) * stride;

    // 3) stage K (hi/lo) and V^T
    for (int i = tid; i < (NTOK * HD) / 4; i += 128) {
        int row = i >> 3, col = (i & 7) * 4;
        float4 k = ((const float4*)(g_qkv + koff))[i];
        float4 v = ((const float4*)(g_qkv + voff))[i];
        float ka[4] = {k.x, k.y, k.z, k.w};
        float va[4] = {v.x, v.y, v.z, v.w};
#pragma unroll
        for (int c = 0; c < 4; c++) {
            float kh = tf32r(ka[c]);
            sm[OFF_KH + row * KSTR + col + c] = kh;
            sm[OFF_KL + row * KSTR + col + c] = tf32r(ka[c] - kh);
            sm[OFF_VT + (col + c) * VSTR + row] = tf32r(va[c]);
        }
    }
    asm volatile("cp.async.wait_group 0;");
    __syncthreads();

    const int wid  = tid >> 5, lane = tid & 31;
    const int g    = lane >> 2, t = lane & 3;
    const int r0   = wid * 16 + g;

    const float* gq = g_qkv + qoff;

    float c[7][4];
#pragma unroll
    for (int j = 0; j < 7; j++)
#pragma unroll
        for (int q = 0; q < 4; q++) c[j][q] = 0.f;

    // QK^T: kc outer; Q fragments from gmem with register hi/lo split
#pragma unroll
    for (int kc = 0; kc < 4; kc++) {
        const int cb = kc * 8 + t;
        float q0 = __ldg(gq + (size_t)r0 * HD + cb);
        float q1 = __ldg(gq + (size_t)(r0 + 8) * HD + cb);
        float q2 = __ldg(gq + (size_t)r0 * HD + cb + 4);
        float q3 = __ldg(gq + (size_t)(r0 + 8) * HD + cb + 4);
        float h0 = tf32r(q0), h1 = tf32r(q1), h2 = tf32r(q2), h3 = tf32r(q3);
        uint32_t ah[4] = {__float_as_uint(h0), __float_as_uint(h1),
                          __float_as_uint(h2), __float_as_uint(h3)};
        uint32_t al[4] = {__float_as_uint(tf32r(q0 - h0)),
                          __float_as_uint(tf32r(q1 - h1)),
                          __float_as_uint(tf32r(q2 - h2)),
                          __float_as_uint(tf32r(q3 - h3))};
#pragma unroll
        for (int j = 0; j < 7; j++) {
            int krow = (j * 8 + g) * KSTR + kc * 8 + t;
            uint32_t bh0 = __float_as_uint(sm[OFF_KH + krow]);
            uint32_t bh1 = __float_as_uint(sm[OFF_KH + krow + 4]);
            uint32_t bl0 = __float_as_uint(sm[OFF_KL + krow]);
            uint32_t bl1 = __float_as_uint(sm[OFF_KL + krow + 4]);
            mma_tf32(c[j], ah, bh0, bh1);
            mma_tf32(c[j], ah, bl0, bl1);
            mma_tf32(c[j], al, bh0, bh1);
        }
    }

    // P = exp2(c*scale*log2e + comb), comb from smem; no max subtraction
    const float scale2 = 0.17677669529663687f * 1.4426950408889634f;
    const float* combs = sm + OFF_CB;

    float s0 = 0.f, s1 = 0.f;
#pragma unroll
    for (int j = 0; j < 7; j++) {
        float2 m0 = *(const float2*)(combs + r0 * NSP + j * 8 + 2 * t);
        float2 m1 = *(const float2*)(combs + (r0 + 8) * NSP + j * 8 + 2 * t);
        float e0 = ex2(fmaf(c[j][0], scale2, m0.x));
        float e1 = ex2(fmaf(c[j][1], scale2, m0.y));
        float e2 = ex2(fmaf(c[j][2], scale2, m1.x));
        float e3 = ex2(fmaf(c[j][3], scale2, m1.y));
        s0 += e0 + e1; s1 += e2 + e3;
        c[j][0] = tf32r(e0); c[j][1] = tf32r(e1);
        c[j][2] = tf32r(e2); c[j][3] = tf32r(e3);
    }
    s0 += __shfl_xor_sync(0xffffffffu, s0, 1);
    s0 += __shfl_xor_sync(0xffffffffu, s0, 2);
    s1 += __shfl_xor_sync(0xffffffffu, s1, 1);
    s1 += __shfl_xor_sync(0xffffffffu, s1, 2);
    const float inv0 = 1.0f / s0, inv1 = 1.0f / s1;

    // AV: P (c-frag -> a-frag via shfl) x V^T
    float acc[4][4];
#pragma unroll
    for (int n = 0; n < 4; n++)
#pragma unroll
        for (int q = 0; q < 4; q++) acc[n][q] = 0.f;

#pragma unroll
    for (int j = 0; j < 7; j++) {
        int src = (g << 2) + (t >> 1);
        float v0 = __shfl_sync(0xffffffffu, c[j][0], src);
        float v1 = __shfl_sync(0xffffffffu, c[j][1], src);
        float v2 = __shfl_sync(0xffffffffu, c[j][2], src);
        float v3 = __shfl_sync(0xffffffffu, c[j][3], src);
        float w0 = __shfl_sync(0xffffffffu, c[j][0], src + 2);
        float w1 = __shfl_sync(0xffffffffu, c[j][1], src + 2);
        float w2 = __shfl_sync(0xffffffffu, c[j][2], src + 2);
        float w3 = __shfl_sync(0xffffffffu, c[j][3], src + 2);
        uint32_t a[4];
        a[0] = __float_as_uint((t & 1) ? v1 : v0);
        a[1] = __float_as_uint((t & 1) ? v3 : v2);
        a[2] = __float_as_uint((t & 1) ? w1 : w0);
        a[3] = __float_as_uint((t & 1) ? w3 : w2);
#pragma unroll
        for (int n = 0; n < 4; n++) {
            int vrow = (n * 8 + g) * VSTR + j * 8 + t;
            uint32_t b0 = __float_as_uint(sm[OFF_VT + vrow]);
            uint32_t b1 = __float_as_uint(sm[OFF_VT + vrow + 4]);
            mma_tf32(acc[n], a, b0, b1);
        }
    }

#pragma unroll
    for (int n = 0; n < 4; n++) {
        int col = h * HD + n * 8 + 2 * t;
        if (r0 < NTOK) {
            float2 o = make_float2(tf32r(acc[n][0] * inv0),
                                   tf32r(acc[n][1] * inv0));
            *(float2*)&g_y[((size_t)b * NTOK + r0) * EMB + col] = o;
        }
        if (r0 + 8 < NTOK) {
            float2 o = make_float2(tf32r(acc[n][2] * inv1),
                                   tf32r(acc[n][3] * inv1));
            *(float2*)&g_y[((size_t)b * NTOK + r0 + 8) * EMB + col] = o;
        }
    }
}

// ---------------------------------------------------------------------------
extern "C" void kernel_launch(void* const* d_in, const int* in_sizes, int n_in,
                              void* d_out, int out_size)
{
    const float* x      = (const float*)d_in[0];
    const float* mask   = (const float*)d_in[1];
    const float* qkv_w  = (const float*)d_in[2];
    const float* qkv_b  = (const float*)d_in[3];
    const float* proj_w = (const float*)d_in[4];
    const float* proj_b = (const float*)d_in[5];
    const float* rpb    = (const float*)d_in[6];
    const int*   rel_idx= (const int*)  d_in[7];
    float* out = (float*)d_out;

    cudaFuncSetAttribute(mma_gemm<0>,
        cudaFuncAttributeMaxDynamicSharedMemorySize, SMEM_BYTES);
    cudaFuncSetAttribute(mma_gemm<1>,
        cudaFuncAttributeMaxDynamicSharedMemorySize, SMEM_BYTES);

    // K0: weight rounding (tiny) + combined bias table
    {
        int w4 = QKV_O * KDIM / 4;
        cvt_tf32_kernel<1><<<(w4 + 255) / 256, 256>>>((const float4*)qkv_w, w4);
        int p4 = EMB * KDIM / 4;
        cvt_tf32_kernel<2><<<(p4 + 255) / 256, 256>>>((const float4*)proj_w, p4);
        int nb = NWIN * HEADS * NTP * NSP;
        prep_bias<<<(nb + 255) / 256, 256>>>(mask, rpb, rel_idx);
    }
    // K1: qkv GEMM
    {
        dim3 grid(QKV_O / 128, MROWS / 128);
        mma_gemm<0><<<grid, 128, SMEM_BYTES>>>(x, qkv_b, nullptr);
    }
    // K2: attention
    {
        dim3 grid(BATCH, HEADS);
        attn_kernel<<<grid, 128>>>();
    }
    // K3: proj GEMM
    {
        dim3 grid(EMB / 128, MROWS / 128);
        mma_gemm<1><<<grid, 128, SMEM_BYTES>>>(g_y /*unused*/, proj_b, out);
    }
}